// round 10
// baseline (speedup 1.0000x reference)
#include <cuda_runtime.h>

// ---------------------------------------------------------------------------
// Fused BasicBlockA, round 10 (= round 9 + epilogue task-count fix).
//  - Block 256 thr = 8 warps, tile 32x8. Warp w processes latents {w, w+8}
//    fully independently: stage-1 h -> own SMEM buffer, stage-2 -> register
//    accumulators. Only __syncwarp inside the loop.
//  - f32x2 packed math over vertical row pairs (FFMA2), cmb() for odd rows.
//  - Odd u64 row strides (37/35) against stride-2 bank conflicts.
//  - Final: one __syncthreads, 8-way partial reduction (384 tasks, strided
//    over 256 threads), + mean + gated residual.
// ---------------------------------------------------------------------------

#define L_DIM 16
#define TX 32
#define TY 8
#define NT 256
#define WARPS 8
#define XQ 6         // x pair q = x rel rows (2q-4, 2q-3): rows -4..7
#define HQ 5         // h pair hq = h rel rows (2hq-2, 2hq-1): rows -2..7
#define XCOLS 37     // x store col = rel col + 2 (rel -2..33), odd pad
#define HCOLS 35     // h store col = rel col + 1 (rel -1..32), odd pad
#define NS1 85       // stage-1 tasks: 5 pair-rows x 17 col-pairs
#define NRED 384     // reduction tasks: 64 quads x 6 (ch x colA/B)

typedef unsigned long long u64;

struct WB2 {
    float w[2][L_DIM][3][16];  // [stage][latent][j][chunk16]
    u64   b[L_DIM][3];
};
__device__ WB2 g_wb;

__device__ __forceinline__ float softplus_f(float v) {
    return fmaxf(v, 0.f) + log1pf(expf(-fabsf(v)));
}
__device__ __forceinline__ u64 pack2(float lo, float hi) {
    u64 r; asm("mov.b64 %0, {%1, %2};" : "=l"(r) : "f"(lo), "f"(hi)); return r;
}
__device__ __forceinline__ void unpack2(u64 v, float& lo, float& hi) {
    asm("mov.b64 {%0, %1}, %2;" : "=f"(lo), "=f"(hi) : "l"(v));
}
__device__ __forceinline__ u64 fma2(u64 a, u64 b, u64 c) {
    u64 d; asm("fma.rn.f32x2 %0, %1, %2, %3;" : "=l"(d) : "l"(a), "l"(b), "l"(c)); return d;
}
__device__ __forceinline__ u64 dup2(float f) { return pack2(f, f); }
__device__ __forceinline__ u64 cmb(u64 A, u64 B) {   // (A.hi, B.lo)
    float al, ah, bl, bh;
    unpack2(A, al, ah); unpack2(B, bl, bh);
    return pack2(ah, bl);
}

__device__ __host__ __forceinline__ constexpr int goff(int j, int i) {
    constexpr int t[3][3] = {{0, 5, 10}, {0, 4, 9}, {0, 4, 8}};
    return t[j][i];
}

__global__ void prep_kernel(const float* __restrict__ w1, const float* __restrict__ c1,
                            const float* __restrict__ bias1,
                            const float* __restrict__ w2, const float* __restrict__ c2) {
    int t = threadIdx.x;
    if (t >= 2 * L_DIM) return;
    int stage = t >> 4;
    int l = t & 15;
    const float* W = stage ? w2 : w1;
    const float* C = stage ? c2 : c1;
    for (int j = 0; j < 3; j++) {
        float* dst = g_wb.w[stage][l][j];
        for (int k = 0; k < 16; k++) dst[k] = 0.f;
        for (int i = 0; i < 3; i++) {
            int base = ((l * 3 + i) * 3 + j) * 9;
            int k = goff(j, i);
            dst[k + 0] = W[base + 0];
            dst[k + 1] = W[base + 1];
            dst[k + 2] = W[base + 2];
            dst[k + 3] = W[base + 3];
            if (j <= i)
                dst[k + 4] = (j == i) ? softplus_f(C[base + 4]) : W[base + 4];
        }
    }
    if (stage == 0)
        for (int i = 0; i < 3; i++) g_wb.b[l][i] = dup2(bias1[l * 3 + i]);
}

template <int J>
__device__ __forceinline__ void conv_j(const float (&wf)[16], u64 a[3],
                                       u64 s0, u64 s1, u64 s2, u64 s3, u64 s4) {
#pragma unroll
    for (int i = 0; i < 3; i++) {
        const int k = goff(J, i);
        a[i] = fma2(dup2(wf[k + 0]), s0, a[i]);
        a[i] = fma2(dup2(wf[k + 1]), s1, a[i]);
        a[i] = fma2(dup2(wf[k + 2]), s2, a[i]);
        a[i] = fma2(dup2(wf[k + 3]), s3, a[i]);
        if (J <= i) a[i] = fma2(dup2(wf[k + 4]), s4, a[i]);
    }
}

__device__ __forceinline__ float elu_f(float v) {
    return (v > 0.f) ? v : (__expf(v) - 1.f);
}

// Two adjacent columns at pair-row p: L = tile[p]; M = tile[p+1];
// odd rows via cmb. Output pair = M's rows. aA: col cc, aB: col cc+1.
__device__ __forceinline__ void conv2(const float* __restrict__ wl,
                                      const u64* __restrict__ tile,
                                      int pstride, int chstride, int p, int cc,
                                      u64 aA[3], u64 aB[3]) {
#pragma unroll
    for (int j = 0; j < 3; j++) {
        const u64* tj = tile + j * chstride + p * pstride + cc;
        u64 L0 = tj[0], L1 = tj[1], L2 = tj[2], L3 = tj[3];
        const u64* tm = tj + pstride;
        u64 M0 = tm[0], M1 = tm[1], M2 = tm[2], M3 = tm[3];
        u64 o0 = cmb(L0, M0), o1 = cmb(L1, M1), o2 = cmb(L2, M2), o3 = cmb(L3, M3);
        alignas(16) float wf[16];
        ((float4*)wf)[0] = ((const float4*)(wl + j * 16))[0];
        ((float4*)wf)[1] = ((const float4*)(wl + j * 16))[1];
        ((float4*)wf)[2] = ((const float4*)(wl + j * 16))[2];
        ((float4*)wf)[3] = ((const float4*)(wl + j * 16))[3];
        if (j == 0) { conv_j<0>(wf, aA, o0, o1, o2, M0, M1); conv_j<0>(wf, aB, o1, o2, o3, M1, M2); }
        if (j == 1) { conv_j<1>(wf, aA, o0, o1, o2, M0, M1); conv_j<1>(wf, aB, o1, o2, o3, M1, M2); }
        if (j == 2) { conv_j<2>(wf, aA, o0, o1, o2, M0, M1); conv_j<2>(wf, aB, o1, o2, o3, M1, M2); }
    }
}

__global__ __launch_bounds__(NT)
void fused_kernel(const float* __restrict__ x, const float* __restrict__ res,
                  float* __restrict__ out) {
    __shared__ alignas(16) WB2 swb;
    __shared__ u64 xsE[3][XQ][XCOLS];
    __shared__ u64 hsW[WARPS][3][HQ][HCOLS];   // per-warp h; reused as red buf

    const int tid  = threadIdx.x;
    const int lane = tid & 31;
    const int wrp  = tid >> 5;
    const int b    = blockIdx.z;
    const int gy0  = blockIdx.y * TY;
    const int gx0  = blockIdx.x * TX;

    // ---- weights/bias into SMEM ----
    {
        const u64* src = (const u64*)&g_wb;
        u64* dst = (u64*)&swb;
        const int n = sizeof(WB2) / 8;
        for (int q = tid; q < n; q += NT) dst[q] = src[q];
    }

    // ---- x tile, pair layout ----
    const float* xb = x + (size_t)b * 3 * 128 * 128;
    for (int q = tid; q < 3 * XQ * XCOLS; q += NT) {
        int j  = q / (XQ * XCOLS);
        int r  = (q / XCOLS) % XQ;
        int cc = q % XCOLS;
        int gy = gy0 + 2 * r - 4;
        int gx = gx0 + cc - 2;
        float lo = 0.f, hi = 0.f;
        if ((unsigned)gx < 128u) {
            const float* col = xb + (size_t)j * 128 * 128 + gx;
            if ((unsigned)gy < 128u)       lo = col[(size_t)gy * 128];
            if ((unsigned)(gy + 1) < 128u) hi = col[(size_t)(gy + 1) * 128];
        }
        xsE[j][r][cc] = pack2(lo, hi);
    }
    __syncthreads();

    // ---- stage-1 task slots for this lane (latent-invariant) ----
    int  s_hq[3], s_hc[3];
    bool s_act[3], s_vAlo[3], s_vAhi[3], s_vBlo[3], s_vBhi[3];
#pragma unroll
    for (int it = 0; it < 3; it++) {
        int tk = lane + 32 * it;
        s_act[it] = (tk < NS1);
        int hq = tk / 17, cp = tk % 17;
        if (!s_act[it]) { hq = 0; cp = 0; }
        s_hq[it] = hq;
        s_hc[it] = 2 * cp;
        bool rlo = ((unsigned)(gy0 + 2 * hq - 2) < 128u);
        bool rhi = ((unsigned)(gy0 + 2 * hq - 1) < 128u);
        bool cA  = ((unsigned)(gx0 + 2 * cp - 1) < 128u);
        bool cB  = ((unsigned)(gx0 + 2 * cp) < 128u);
        s_vAlo[it] = cA && rlo; s_vAhi[it] = cA && rhi;
        s_vBlo[it] = cB && rlo; s_vBhi[it] = cB && rhi;
    }

    // stage-2: 2 tasks per thread over 4 out pair-rows x 16 col-pairs
    const int c2c = lane & 15;           // col-pair
    const int op0 = lane >> 4;           // 0..1
    const int op1 = op0 + 2;             // 2..3

    u64* hw = &hsW[wrp][0][0][0];

    u64 acc[2][2][3];                    // [task][colA/B][ch]
#pragma unroll
    for (int t = 0; t < 2; t++)
#pragma unroll
        for (int ab = 0; ab < 2; ab++)
#pragma unroll
            for (int i = 0; i < 3; i++) acc[t][ab][i] = pack2(0.f, 0.f);

    // ---- warp-private latent loop: NO block barriers ----
#pragma unroll 1
    for (int li = 0; li < 2; li++) {
        const int l = wrp + 8 * li;
        const float* w1l = &swb.w[0][l][0][0];
        const u64 bl0 = swb.b[l][0], bl1 = swb.b[l][1], bl2 = swb.b[l][2];

        // stage 1: 85 tasks across the warp
#pragma unroll
        for (int it = 0; it < 3; it++) {
            if (s_act[it]) {
                const int hq = s_hq[it], hc = s_hc[it];
                u64 aA[3] = {bl0, bl1, bl2}, aB[3] = {bl0, bl1, bl2};
                conv2(w1l, &xsE[0][0][0], XCOLS, XQ * XCOLS, hq, hc, aA, aB);
#pragma unroll
                for (int i = 0; i < 3; i++) {
                    float lo, hi;
                    unpack2(aA[i], lo, hi);
                    lo = s_vAlo[it] ? elu_f(lo) : 0.f;
                    hi = s_vAhi[it] ? elu_f(hi) : 0.f;
                    hw[i * (HQ * HCOLS) + hq * HCOLS + hc] = pack2(lo, hi);
                    unpack2(aB[i], lo, hi);
                    lo = s_vBlo[it] ? elu_f(lo) : 0.f;
                    hi = s_vBhi[it] ? elu_f(hi) : 0.f;
                    hw[i * (HQ * HCOLS) + hq * HCOLS + hc + 1] = pack2(lo, hi);
                }
            }
        }
        __syncwarp();

        // stage 2: two tasks, accumulate into registers
        conv2(&swb.w[1][l][0][0], hw, HCOLS, HQ * HCOLS, op0, 2 * c2c,
              acc[0][0], acc[0][1]);
        conv2(&swb.w[1][l][0][0], hw, HCOLS, HQ * HCOLS, op1, 2 * c2c,
              acc[1][0], acc[1][1]);
        __syncwarp();   // all lanes done reading hw before next latent rewrites
    }

    // ---- write per-warp partials into (reused) own hs region ----
    // red index: tk*6 + i*2 + ab ; tk = op*16 + c
    {
        u64* red = hw;
#pragma unroll
        for (int t = 0; t < 2; t++) {
            const int tk = (op0 + 2 * t) * 16 + c2c;
#pragma unroll
            for (int i = 0; i < 3; i++) {
                red[tk * 6 + i * 2 + 0] = acc[t][0][i];
                red[tk * 6 + i * 2 + 1] = acc[t][1][i];
            }
        }
    }
    __syncthreads();

    // ---- 8-way reduction + mean + gated residual + store (384 tasks) ----
    const float rv = res[0];
    const float g = (rv > 0.f) ? rv : 0.f;
    float* ob = out + (size_t)b * 3 * 128 * 128;
    for (int q = tid; q < NRED; q += NT) {
        const int tk = q / 6, r = q % 6;
        const int i = r >> 1, ab = r & 1;
        const int op = tk >> 4, c = tk & 15;
        float slo = 0.f, shi = 0.f;
#pragma unroll
        for (int w = 0; w < WARPS; w++) {
            float lo, hi;
            unpack2(hsW[w][0][0][q], lo, hi);
            slo += lo; shi += hi;
        }
        const int col = 2 * c + ab;
        const int gy = gy0 + 2 * op;
        const int gx = gx0 + col;
        float xlo, xhi;
        unpack2(xsE[i][op + 2][col + 2], xlo, xhi);
        ob[(i * 128 + gy) * 128 + gx]       = slo * (1.f / 16.f) + g * xlo;
        ob[(i * 128 + gy + 1) * 128 + gx]   = shi * (1.f / 16.f) + g * xhi;
    }
}

extern "C" void kernel_launch(void* const* d_in, const int* in_sizes, int n_in,
                              void* d_out, int out_size) {
    const float* x  = (const float*)d_in[0];
    const float* w1 = (const float*)d_in[1];
    const float* c1 = (const float*)d_in[2];
    const float* b1 = (const float*)d_in[3];
    const float* w2 = (const float*)d_in[4];
    const float* c2 = (const float*)d_in[5];
    const float* rs = (const float*)d_in[6];
    (void)in_sizes; (void)n_in; (void)out_size;

    prep_kernel<<<1, 32>>>(w1, c1, b1, w2, c2);

    dim3 grid(128 / TX, 128 / TY, 64);
    fused_kernel<<<grid, NT>>>(x, rs, (float*)d_out);
}